// round 15
// baseline (speedup 1.0000x reference)
#include <cuda_runtime.h>
#include <cuda_fp16.h>
#include <cstdint>

// Problem constants
#define NB      32
#define NHQ     32
#define NKVH    8
#define HDIM    128
#define PASTLEN 2048
#define HID     4096
#define NCOLS   6144          // q(4096) + k(1024) + v(1024)
#define SPLITK  8
#define KSLICE  (HID / SPLITK)

// Attention tiling (R9/R14 configuration — measured best: attn 105.4us)
#define CHUNK    64
#define ASPLIT   4                           // key splits per (b,gq)
#define CH_PER_S (PASTLEN / CHUNK / ASPLIT)  // 8 chunks per split
#define KROW     132
#define NGRP     (NB * NKVH)                 // 256 groups

// Scratch (device globals; runtime allocation forbidden)
__device__ __align__(16) __half g_x[NB * HID];
__device__ __align__(16) float  g_qkvp[SPLITK * NB * NCOLS];
__device__ __align__(16) float  g_op[SPLITK * NB * HID];
__device__ __align__(16) __half g_q[NB * NHQ * HDIM];
__device__ __align__(16) __half g_k[NB * NKVH * HDIM];
__device__ __align__(16) __half g_v[NB * NKVH * HDIM];
__device__ __align__(16) __half g_attn[NB * NHQ * HDIM];
__device__ __align__(16) float  g_po[(size_t)NGRP * ASPLIT * 512];
__device__ __align__(16) float  g_pm[NGRP * ASPLIT * 4];
__device__ __align__(16) float  g_pl[NGRP * ASPLIT * 4];
__device__ int g_isf32;

// ---------------------------------------------------------------------------
// typed helpers
// ---------------------------------------------------------------------------
__device__ __forceinline__ uint4 ld8(const __half* p) { return *(const uint4*)p; }
__device__ __forceinline__ uint4 ld8(const float* p) {
    float4 f0 = *(const float4*)p;
    float4 f1 = *(const float4*)(p + 4);
    __half2 h0 = __floats2half2_rn(f0.x, f0.y);
    __half2 h1 = __floats2half2_rn(f0.z, f0.w);
    __half2 h2 = __floats2half2_rn(f1.x, f1.y);
    __half2 h3 = __floats2half2_rn(f1.z, f1.w);
    uint4 r;
    r.x = *reinterpret_cast<uint32_t*>(&h0);
    r.y = *reinterpret_cast<uint32_t*>(&h1);
    r.z = *reinterpret_cast<uint32_t*>(&h2);
    r.w = *reinterpret_cast<uint32_t*>(&h3);
    return r;
}
__device__ __forceinline__ void ld4f(const __half* p, float* f) {
    uint2 u = *(const uint2*)p;
    float2 fa = __half22float2(*(__half2*)&u.x);
    float2 fb = __half22float2(*(__half2*)&u.y);
    f[0] = fa.x; f[1] = fa.y; f[2] = fb.x; f[3] = fb.y;
}
__device__ __forceinline__ void ld4f(const float* p, float* f) {
    float4 v = *(const float4*)p;
    f[0] = v.x; f[1] = v.y; f[2] = v.z; f[3] = v.w;
}
// streaming (evict-first) variants for once-read KV cache rows
__device__ __forceinline__ void ld4f_cs(const __half* p, float* f) {
    uint2 u = __ldcs((const uint2*)p);
    float2 fa = __half22float2(*(__half2*)&u.x);
    float2 fb = __half22float2(*(__half2*)&u.y);
    f[0] = fa.x; f[1] = fa.y; f[2] = fb.x; f[3] = fb.y;
}
__device__ __forceinline__ void ld4f_cs(const float* p, float* f) {
    float4 v = __ldcs((const float4*)p);
    f[0] = v.x; f[1] = v.y; f[2] = v.z; f[3] = v.w;
}
__device__ __forceinline__ float ldf1(const void* p, int i) {
    return g_isf32 ? ((const float*)p)[i] : __half2float(((const __half*)p)[i]);
}

// ---------------------------------------------------------------------------
// m16n8k16 f16 MMA (f32 accumulate)
// ---------------------------------------------------------------------------
__device__ __forceinline__ void mma16816(float* d,
                                         uint32_t a0, uint32_t a1, uint32_t a2, uint32_t a3,
                                         uint32_t b0, uint32_t b1) {
    asm volatile(
        "mma.sync.aligned.m16n8k16.row.col.f32.f16.f16.f32 "
        "{%0,%1,%2,%3},{%4,%5,%6,%7},{%8,%9},{%0,%1,%2,%3};\n"
        : "+f"(d[0]), "+f"(d[1]), "+f"(d[2]), "+f"(d[3])
        : "r"(a0), "r"(a1), "r"(a2), "r"(a3), "r"(b0), "r"(b1));
}

// ---------------------------------------------------------------------------
// Kernel 1: x convert to fp16 (+ fused dtype probe)
// ---------------------------------------------------------------------------
__global__ void __launch_bounds__(256) xconv_kernel(const void* xv) {
    int e0 = (blockIdx.x * 256 + threadIdx.x) * 8;
    const uint32_t* w = (const uint32_t*)xv + (e0 >> 1);
    int good16 = 0, good32 = 0;
#pragma unroll
    for (int i = 0; i < 4; i++) {
        uint32_t u = w[i];
        float a = __half2float(__ushort_as_half((unsigned short)(u & 0xFFFFu)));
        float bb = __half2float(__ushort_as_half((unsigned short)(u >> 16)));
        if (isfinite(a) && isfinite(bb) &&
            fabsf(a) > 0.004f && fabsf(a) < 8.f &&
            fabsf(bb) > 0.004f && fabsf(bb) < 8.f) good16++;
        float f = __uint_as_float(u);
        if (isfinite(f) && fabsf(f) > 0.004f && fabsf(f) < 8.f) good32++;
    }
#pragma unroll
    for (int off = 16; off > 0; off >>= 1) {
        good16 += __shfl_xor_sync(0xffffffffu, good16, off);
        good32 += __shfl_xor_sync(0xffffffffu, good32, off);
    }
    int isf32 = good32 > good16;
    if (blockIdx.x == 0 && threadIdx.x == 0) g_isf32 = isf32;

    uint4 out;
    if (isf32) out = ld8((const float*)xv + e0);
    else       out = *((const uint4*)xv + (e0 >> 3));
    *(uint4*)(g_x + e0) = out;
}

// ---------------------------------------------------------------------------
// Kernel 2: QKV projection, split-K=8, unroll 8 (deeper weight-load MLP).
// grid = 96*8 = 768 blocks x 256.
// ---------------------------------------------------------------------------
template<typename T>
__device__ __forceinline__ void qkv_sk(const T* __restrict__ w, int wrow0,
                                       float* __restrict__ out, int ocol0, int k0) {
    const int warp = threadIdx.x >> 5;
    const int lane = threadIdx.x & 31;
    const int g = lane >> 2;
    const int c = lane & 3;

    const T* wrow = w + (size_t)(wrow0 + warp * 8 + g) * HID + k0 + 8 * c;
    const __half* x0 = g_x + (size_t)g * HID + k0 + 8 * c;

    float d0[4] = {0.f, 0.f, 0.f, 0.f};
    float d1[4] = {0.f, 0.f, 0.f, 0.f};

#pragma unroll 8
    for (int kb = 0; kb < KSLICE; kb += 32) {
        uint4 bv = ld8(wrow + kb);
        uint4 xa = ld8(x0 + kb);
        uint4 xb = ld8(x0 + 8 * HID + kb);
        uint4 xc = ld8(x0 + 16 * HID + kb);
        uint4 xd = ld8(x0 + 24 * HID + kb);
        mma16816(d0, xa.x, xb.x, xa.y, xb.y, bv.x, bv.y);
        mma16816(d1, xc.x, xd.x, xc.y, xd.y, bv.x, bv.y);
        mma16816(d0, xa.z, xb.z, xa.w, xb.w, bv.z, bv.w);
        mma16816(d1, xc.z, xd.z, xc.w, xd.w, bv.z, bv.w);
    }

    const int oc = ocol0 + warp * 8 + 2 * c;
    *(float2*)(out + (size_t)(g)      * NCOLS + oc) = make_float2(d0[0], d0[1]);
    *(float2*)(out + (size_t)(g + 8)  * NCOLS + oc) = make_float2(d0[2], d0[3]);
    *(float2*)(out + (size_t)(g + 16) * NCOLS + oc) = make_float2(d1[0], d1[1]);
    *(float2*)(out + (size_t)(g + 24) * NCOLS + oc) = make_float2(d1[2], d1[3]);
}
__global__ void __launch_bounds__(256) qkv_kernel(const void* wq, const void* wk, const void* wv) {
    int nt = blockIdx.x >> 3;
    int ks = blockIdx.x & 7;
    int ncol = nt * 64;
    int k0 = ks * KSLICE;
    float* out = g_qkvp + (size_t)ks * NB * NCOLS;
    const void* w;
    int wrow0;
    if (ncol < 4096)      { w = wq; wrow0 = ncol; }
    else if (ncol < 5120) { w = wk; wrow0 = ncol - 4096; }
    else                  { w = wv; wrow0 = ncol - 5120; }
    if (g_isf32) qkv_sk<float >((const float*)w, wrow0, out, ncol, k0);
    else         qkv_sk<__half>((const __half*)w, wrow0, out, ncol, k0);
}

// ---------------------------------------------------------------------------
// Kernel 3: qkv combine -> g_q / g_k / g_v (fp16)
// ---------------------------------------------------------------------------
__global__ void __launch_bounds__(256) qkvcomb_kernel() {
    int idx = blockIdx.x * 256 + threadIdx.x;
    int m = idx / NCOLS, ncol = idx - m * NCOLS;
    float s = 0.f;
#pragma unroll
    for (int ks = 0; ks < SPLITK; ks++) s += g_qkvp[(size_t)ks * NB * NCOLS + idx];
    __half h = __float2half(s);
    if (ncol < 4096)      g_q[m * 4096 + ncol] = h;
    else if (ncol < 5120) g_k[m * 1024 + ncol - 4096] = h;
    else                  g_v[m * 1024 + ncol - 5120] = h;
}

// ---------------------------------------------------------------------------
// Kernel 4: split-K flash-decode attention (R14 body, byte-identical).
// grid = NGRP * ASPLIT = 1024 blocks x 256 threads.
// ---------------------------------------------------------------------------
#define ATTN_SMEM_BYTES (CHUNK*KROW*2*2 + 512*4 /*q*/ + CHUNK*4*4 /*p*/ + 16*CHUNK*4 /*s_part*/ + 64*4)

template<typename T>
__device__ __forceinline__ void attn_body(const T* __restrict__ kv,
                                          const int* __restrict__ sel,
                                          const void* __restrict__ cos_,
                                          const void* __restrict__ sin_) {
    extern __shared__ char smem_raw[];
    __half* k_sm   = (__half*)smem_raw;                 // [CHUNK][KROW]
    __half* v_sm   = k_sm + CHUNK * KROW;               // [CHUNK][KROW]
    float*  q_sm   = (float*)(v_sm + CHUNK * KROW);     // [4][128]
    float*  p_sm   = q_sm + 512;                        // [4][CHUNK]
    float*  s_part = p_sm + 4 * CHUNK;                  // [4][4][CHUNK]
    float*  wred   = s_part + 16 * CHUNK;               // [8]
    float*  m_run  = wred + 8;                          // [4]
    float*  l_run  = m_run + 4;                         // [4]
    float*  al_sm  = l_run + 4;                         // [4]

    const int grp  = blockIdx.x >> 2;
    const int sp   = blockIdx.x & 3;
    const int b    = grp >> 3;
    const int gq   = grp & 7;
    const int t    = threadIdx.x;
    const int warp = t >> 5;
    const int lane = t & 31;
    const float scale = 0.08838834764831845f;

    // q into smem with RoPE fused
    for (int i = t; i < 512; i += 256) {
        int r = i >> 7, d = i & 127;
        const __half* qr = g_q + (size_t)(b * NHQ + gq * 4 + r) * HDIM;
        float q0 = __half2float(qr[d]);
        float q1 = __half2float(qr[d ^ 64]);
        float cv = ldf1(cos_, b * HDIM + d);
        float sv = ldf1(sin_, b * HDIM + d);
        float rot = (d < 64) ? -q1 : q1;
        q_sm[i] = fmaf(q0, cv, rot * sv) * scale;
    }
    if (t < 4) { m_run[t] = -1e30f; l_run[t] = 0.f; }
    __syncthreads();

    float o[4][4];
#pragma unroll
    for (int r = 0; r < 4; r++)
#pragma unroll
        for (int i = 0; i < 4; i++) o[r][i] = 0.f;

    // Last split's prologue: the new token (roped k)
    if (sp == ASPLIT - 1) {
        if (warp < 4) {
            const int r = warp;
            const __half* kr = g_k + (size_t)(b * NKVH + gq) * HDIM;
            float part = 0.f;
            const float* qrp = q_sm + r * 128 + lane * 4;
#pragma unroll
            for (int i = 0; i < 4; i++) {
                int d = lane * 4 + i;
                float k0 = __half2float(kr[d]);
                float k1 = __half2float(kr[d ^ 64]);
                float cv = ldf1(cos_, b * HDIM + d);
                float sv = ldf1(sin_, b * HDIM + d);
                float rot = (d < 64) ? -k1 : k1;
                part = fmaf(qrp[i], fmaf(k0, cv, rot * sv), part);
            }
#pragma unroll
            for (int off = 16; off > 0; off >>= 1)
                part += __shfl_xor_sync(0xffffffffu, part, off);
            if (lane == 0) { m_run[r] = part; l_run[r] = 1.f; }
        }
        if (warp == 0) {
            float vf[4];
            ld4f(g_v + (size_t)(b * NKVH + gq) * HDIM + lane * 4, vf);
#pragma unroll
            for (int r = 0; r < 4; r++)
#pragma unroll
                for (int i = 0; i < 4; i++) o[r][i] = vf[i];
        }
        __syncthreads();
    }

    const int selbase = b * PASTLEN;

    for (int ch = 0; ch < CH_PER_S; ch++) {
        const int key0 = (sp * CH_PER_S + ch) * CHUNK;

        // stage K/V -> smem fp16 : warp w handles rows [8w, 8w+8); streaming loads
#pragma unroll
        for (int i = 0; i < CHUNK / 8; i++) {
            int j = warp * (CHUNK / 8) + i;
            int row = __ldg(sel + selbase + key0 + j);
            const T* kp = kv + (size_t)row * (2 * NKVH * HDIM) + gq * HDIM + lane * 4;
            const T* vp = kp + NKVH * HDIM;
            float kf[4], vf[4];
            ld4f_cs(kp, kf);
            ld4f_cs(vp, vf);
            __half2 ka = __floats2half2_rn(kf[0], kf[1]);
            __half2 kb = __floats2half2_rn(kf[2], kf[3]);
            __half2 va = __floats2half2_rn(vf[0], vf[1]);
            __half2 vb = __floats2half2_rn(vf[2], vf[3]);
            uint2 kw, vw;
            kw.x = *reinterpret_cast<uint32_t*>(&ka); kw.y = *reinterpret_cast<uint32_t*>(&kb);
            vw.x = *reinterpret_cast<uint32_t*>(&va); vw.y = *reinterpret_cast<uint32_t*>(&vb);
            *(uint2*)(k_sm + j * KROW + lane * 4) = kw;
            *(uint2*)(v_sm + j * KROW + lane * 4) = vw;
        }
        __syncthreads();

        // scores: thread -> (key j = t&63, quarter qh = t>>6 -> dims [32qh, 32qh+32))
        {
            const int j  = t & 63;
            const int qh = t >> 6;
            const __half* kr = k_sm + j * KROW + qh * 32;
            const float* q0 = q_sm + 0 * 128 + qh * 32;
            const float* q1 = q_sm + 1 * 128 + qh * 32;
            const float* q2 = q_sm + 2 * 128 + qh * 32;
            const float* q3 = q_sm + 3 * 128 + qh * 32;
            float s0 = 0.f, s1 = 0.f, s2 = 0.f, s3 = 0.f;
#pragma unroll
            for (int d = 0; d < 32; d += 4) {
                float kf[4];
                ld4f(kr + d, kf);
                float4 a0 = *(const float4*)(q0 + d);
                float4 a1 = *(const float4*)(q1 + d);
                float4 a2 = *(const float4*)(q2 + d);
                float4 a3 = *(const float4*)(q3 + d);
                s0 = fmaf(a0.x, kf[0], fmaf(a0.y, kf[1], fmaf(a0.z, kf[2], fmaf(a0.w, kf[3], s0))));
                s1 = fmaf(a1.x, kf[0], fmaf(a1.y, kf[1], fmaf(a1.z, kf[2], fmaf(a1.w, kf[3], s1))));
                s2 = fmaf(a2.x, kf[0], fmaf(a2.y, kf[1], fmaf(a2.z, kf[2], fmaf(a2.w, kf[3], s2))));
                s3 = fmaf(a3.x, kf[0], fmaf(a3.y, kf[1], fmaf(a3.z, kf[2], fmaf(a3.w, kf[3], s3))));
            }
            s_part[(qh * 4 + 0) * CHUNK + j] = s0;
            s_part[(qh * 4 + 1) * CHUNK + j] = s1;
            s_part[(qh * 4 + 2) * CHUNK + j] = s2;
            s_part[(qh * 4 + 3) * CHUNK + j] = s3;
        }
        __syncthreads();

        // block softmax: thread -> (head r = t>>6, key j = t&63)
        {
            const int r = t >> 6;
            const int j = t & 63;
            float s = s_part[(0 * 4 + r) * CHUNK + j] + s_part[(1 * 4 + r) * CHUNK + j]
                    + s_part[(2 * 4 + r) * CHUNK + j] + s_part[(3 * 4 + r) * CHUNK + j];
            float mx = s;
#pragma unroll
            for (int off = 16; off > 0; off >>= 1)
                mx = fmaxf(mx, __shfl_xor_sync(0xffffffffu, mx, off));
            if (lane == 0) wred[warp] = mx;
            __syncthreads();
            if (t < 4) {
                float mn = fmaxf(m_run[t], fmaxf(wred[2 * t], wred[2 * t + 1]));
                al_sm[t] = __expf(m_run[t] - mn);
                m_run[t] = mn;
            }
            __syncthreads();
            float p = __expf(s - m_run[r]);
            p_sm[r * CHUNK + j] = p;
            float ps = p;
#pragma unroll
            for (int off = 16; off > 0; off >>= 1)
                ps += __shfl_xor_sync(0xffffffffu, ps, off);
            if (lane == 0) wred[warp] = ps;
            __syncthreads();
            if (t < 4)
                l_run[t] = l_run[t] * al_sm[t] + wred[2 * t] + wred[2 * t + 1];
        }

        // PV: warp w -> keys j ≡ w (mod 8)
        {
            float a0 = al_sm[0], a1 = al_sm[1], a2 = al_sm[2], a3 = al_sm[3];
#pragma unroll
            for (int i = 0; i < 4; i++) {
                o[0][i] *= a0; o[1][i] *= a1; o[2][i] *= a2; o[3][i] *= a3;
            }
#pragma unroll
            for (int kk = 0; kk < CHUNK / 8; kk++) {
                int j = warp + kk * 8;
                float vf[4];
                ld4f(v_sm + j * KROW + lane * 4, vf);
                float p0 = p_sm[0 * CHUNK + j];
                float p1 = p_sm[1 * CHUNK + j];
                float p2 = p_sm[2 * CHUNK + j];
                float p3 = p_sm[3 * CHUNK + j];
#pragma unroll
                for (int i = 0; i < 4; i++) {
                    o[0][i] = fmaf(p0, vf[i], o[0][i]);
                    o[1][i] = fmaf(p1, vf[i], o[1][i]);
                    o[2][i] = fmaf(p2, vf[i], o[2][i]);
                    o[3][i] = fmaf(p3, vf[i], o[3][i]);
                }
            }
        }
        __syncthreads();
    }

    // merge 8 per-warp accumulators, write unnormalized split result
    float* scratch = (float*)smem_raw;
#pragma unroll
    for (int r = 0; r < 4; r++) {
        float4 v = make_float4(o[r][0], o[r][1], o[r][2], o[r][3]);
        *(float4*)(scratch + (warp * 512 + r * 128 + lane * 4)) = v;
    }
    __syncthreads();
    for (int s = t; s < 512; s += 256) {
        float acc = 0.f;
#pragma unroll
        for (int w = 0; w < 8; w++) acc += scratch[w * 512 + s];
        g_po[(size_t)blockIdx.x * 512 + s] = acc;
    }
    if (t < 4) {
        g_pm[blockIdx.x * 4 + t] = m_run[t];
        g_pl[blockIdx.x * 4 + t] = l_run[t];
    }
}
__global__ void __launch_bounds__(256) attn_kernel(const void* kv, const int* sel,
                                                   const void* cos_, const void* sin_) {
    if (g_isf32) attn_body<float>((const float*)kv, sel, cos_, sin_);
    else         attn_body<__half>((const __half*)kv, sel, cos_, sin_);
}

// ---------------------------------------------------------------------------
// Kernel 4b: merge ASPLIT splits per group -> g_attn
// grid = NGRP (256), block = 512
// ---------------------------------------------------------------------------
__global__ void __launch_bounds__(512) attncomb_kernel() {
    const int grp = blockIdx.x;
    const int r = threadIdx.x >> 7;
    const int d = threadIdx.x & 127;
    const int b = grp >> 3, gq = grp & 7;

    float ms[ASPLIT];
    float M = -1e30f;
#pragma unroll
    for (int s = 0; s < ASPLIT; s++) {
        ms[s] = g_pm[(grp * ASPLIT + s) * 4 + r];
        M = fmaxf(M, ms[s]);
    }
    float L = 0.f, O = 0.f;
#pragma unroll
    for (int s = 0; s < ASPLIT; s++) {
        float al = __expf(ms[s] - M);
        L = fmaf(al, g_pl[(grp * ASPLIT + s) * 4 + r], L);
        O = fmaf(al, g_po[(size_t)(grp * ASPLIT + s) * 512 + r * 128 + d], O);
    }
    g_attn[(size_t)(b * NHQ + gq * 4 + r) * HDIM + d] = __float2half(O / L);
}

// ---------------------------------------------------------------------------
// Kernel 5: output projection, split-K=8, DOUBLE-BUFFERED wo tiles:
// prefetch tile ch+1 into registers while MMAs run on tile ch.
// grid = 64*8 = 512 blocks x 256.
// ---------------------------------------------------------------------------
#define WTROW 72
#define NTILE (KSLICE / 64)   // 8 tiles per block

__global__ void __launch_bounds__(256) outproj_kernel(const void* wo) {
    __shared__ __align__(16) __half wt[2][64 * WTROW];

    const int nt = blockIdx.x >> 3;
    const int ks = blockIdx.x & 7;
    const int h0 = nt * 64;
    const int k0 = ks * KSLICE;

    const int t    = threadIdx.x;
    const int warp = t >> 5;
    const int lane = t & 31;
    const int g = lane >> 2;
    const int c = lane & 3;
    const int tx = t & 63;
    const int ty = t >> 6;

    const int isf = g_isf32;
    const float*  Wf = (const float*)wo;
    const __half* Wh = (const __half*)wo;

    // per-thread tile fetch: 16 rows (j = ty + 4i), column h0+tx
    auto fetch = [&](int o0, float* r) {
#pragma unroll
        for (int i = 0; i < 16; i++) {
            int j = ty + i * 4;
            size_t idx = (size_t)(o0 + j) * HID + h0 + tx;
            r[i] = isf ? Wf[idx] : __half2float(Wh[idx]);
        }
    };
    auto store = [&](int buf, const float* r) {
#pragma unroll
        for (int i = 0; i < 16; i++)
            wt[buf][tx * WTROW + ty + i * 4] = __float2half(r[i]);
    };

    float d0[4] = {0.f, 0.f, 0.f, 0.f};
    float d1[4] = {0.f, 0.f, 0.f, 0.f};
    const __half* x0 = g_attn + (size_t)g * HID + 8 * c;

    float rbuf[16];
    fetch(k0, rbuf);
    store(0, rbuf);
    __syncthreads();

    for (int ch = 0; ch < NTILE; ch++) {
        const int o0 = k0 + ch * 64;
        const int buf = ch & 1;

        if (ch + 1 < NTILE) fetch(o0 + 64, rbuf);   // overlap with MMAs below

#pragma unroll
        for (int kb = 0; kb < 64; kb += 32) {
            uint4 bv = *(const uint4*)(wt[buf] + (warp * 8 + g) * WTROW + kb + 8 * c);
            uint4 xa = ld8(x0 + o0 + kb);
            uint4 xb = ld8(x0 + 8 * HID + o0 + kb);
            uint4 xc = ld8(x0 + 16 * HID + o0 + kb);
            uint4 xd = ld8(x0 + 24 * HID + o0 + kb);
            mma16816(d0, xa.x, xb.x, xa.y, xb.y, bv.x, bv.y);
            mma16816(d1, xc.x, xd.x, xc.y, xd.y, bv.x, bv.y);
            mma16816(d0, xa.z, xb.z, xa.w, xb.w, bv.z, bv.w);
            mma16816(d1, xc.z, xd.z, xc.w, xd.w, bv.z, bv.w);
        }

        if (ch + 1 < NTILE) store(buf ^ 1, rbuf);   // other buffer — no hazard
        __syncthreads();
    }

    float* out = g_op + (size_t)ks * NB * HID;
    const int oc = h0 + warp * 8 + 2 * c;
    *(float2*)(out + (size_t)(g)      * HID + oc) = make_float2(d0[0], d0[1]);
    *(float2*)(out + (size_t)(g + 8)  * HID + oc) = make_float2(d0[2], d0[3]);
    *(float2*)(out + (size_t)(g + 16) * HID + oc) = make_float2(d1[0], d1[1]);
    *(float2*)(out + (size_t)(g + 24) * HID + oc) = make_float2(d1[2], d1[3]);
}

// ---------------------------------------------------------------------------
// Kernel 6: out combine -> d_out (typed)
// ---------------------------------------------------------------------------
__global__ void __launch_bounds__(256) outcomb_kernel(void* y) {
    int idx = blockIdx.x * 256 + threadIdx.x;
    float s = 0.f;
#pragma unroll
    for (int ks = 0; ks < SPLITK; ks++) s += g_op[(size_t)ks * NB * HID + idx];
    if (g_isf32) ((float*)y)[idx] = s;
    else         ((__half*)y)[idx] = __float2half(s);
}

// ---------------------------------------------------------------------------
extern "C" void kernel_launch(void* const* d_in, const int* in_sizes, int n_in,
                              void* d_out, int out_size) {
    (void)out_size;
    const void *x = nullptr, *wq = nullptr, *wk = nullptr, *wv = nullptr, *wo = nullptr;
    const void *cosp = nullptr, *sinp = nullptr, *kvb = nullptr;
    const int* sel = nullptr;
    int ix = -1, ibig0 = -1, ibig1 = -1;
    for (int i = 0; i < n_in; i++) {
        int s = in_sizes[i];
        if      (s == 131072)    { x = d_in[i]; ix = i; }
        else if (s == 136314880) { kvb = d_in[i]; }
        else if (s == 65536)     { sel = (const int*)d_in[i]; }
        else if (s == 16777216)  { if (ibig0 < 0) ibig0 = i; else ibig1 = i; }
        else if (s == 4194304)   { if (!wk) wk = d_in[i]; else wv = d_in[i]; }
        else if (s == 4096)      { if (!cosp) cosp = d_in[i]; else sinp = d_in[i]; }
    }
    if (ibig0 == ix + 1)      { wq = d_in[ibig0]; wo = d_in[ibig1]; }   // dict order
    else if (ix == n_in - 1)  { wo = d_in[ibig0]; wq = d_in[ibig1]; }   // alphabetical
    else                      { wq = d_in[ibig0]; wo = d_in[ibig1]; }

    static int smem_set = 0;
    if (!smem_set) {
        cudaFuncSetAttribute(attn_kernel, cudaFuncAttributeMaxDynamicSharedMemorySize,
                             ATTN_SMEM_BYTES);
        smem_set = 1;
    }

    xconv_kernel<<<64, 256>>>(x);
    qkv_kernel<<<96 * SPLITK, 256>>>(wq, wk, wv);
    qkvcomb_kernel<<<NB * NCOLS / 256, 256>>>();
    attn_kernel<<<NGRP * ASPLIT, 256, ATTN_SMEM_BYTES>>>(kvb, sel, cosp, sinp);
    attncomb_kernel<<<NGRP, 512>>>();
    outproj_kernel<<<64 * SPLITK, 256>>>(wo);
    outcomb_kernel<<<NB * HID / 256, 256>>>(d_out);
}

// round 16
// speedup vs baseline: 1.0563x; 1.0563x over previous
#include <cuda_runtime.h>
#include <cuda_fp16.h>
#include <cstdint>

// Problem constants
#define NB      32
#define NHQ     32
#define NKVH    8
#define HDIM    128
#define PASTLEN 2048
#define HID     4096
#define NCOLS   6144          // q(4096) + k(1024) + v(1024)
#define SPLITK  8
#define KSLICE  (HID / SPLITK)

// Attention tiling (R9/R14 configuration — measured best: attn 105.4us)
#define CHUNK    64
#define ASPLIT   4                           // key splits per (b,gq)
#define CH_PER_S (PASTLEN / CHUNK / ASPLIT)  // 8 chunks per split
#define KROW     132
#define NGRP     (NB * NKVH)                 // 256 groups

// Scratch (device globals; runtime allocation forbidden)
__device__ __align__(16) __half g_x[NB * HID];
__device__ __align__(16) float  g_qkvp[SPLITK * NB * NCOLS];
__device__ __align__(16) float  g_op[SPLITK * NB * HID];
__device__ __align__(16) __half g_q[NB * NHQ * HDIM];
__device__ __align__(16) __half g_k[NB * NKVH * HDIM];
__device__ __align__(16) __half g_v[NB * NKVH * HDIM];
__device__ __align__(16) __half g_attn[NB * NHQ * HDIM];
__device__ __align__(16) float  g_po[(size_t)NGRP * ASPLIT * 512];
__device__ __align__(16) float  g_pm[NGRP * ASPLIT * 4];
__device__ __align__(16) float  g_pl[NGRP * ASPLIT * 4];
__device__ int g_isf32;

// ---------------------------------------------------------------------------
// typed helpers
// ---------------------------------------------------------------------------
__device__ __forceinline__ uint4 ld8(const __half* p) { return *(const uint4*)p; }
__device__ __forceinline__ uint4 ld8(const float* p) {
    float4 f0 = *(const float4*)p;
    float4 f1 = *(const float4*)(p + 4);
    __half2 h0 = __floats2half2_rn(f0.x, f0.y);
    __half2 h1 = __floats2half2_rn(f0.z, f0.w);
    __half2 h2 = __floats2half2_rn(f1.x, f1.y);
    __half2 h3 = __floats2half2_rn(f1.z, f1.w);
    uint4 r;
    r.x = *reinterpret_cast<uint32_t*>(&h0);
    r.y = *reinterpret_cast<uint32_t*>(&h1);
    r.z = *reinterpret_cast<uint32_t*>(&h2);
    r.w = *reinterpret_cast<uint32_t*>(&h3);
    return r;
}
// streaming (evict-first) weight loads — read-once data
__device__ __forceinline__ uint4 ld8_cs(const __half* p) { return __ldcs((const uint4*)p); }
__device__ __forceinline__ uint4 ld8_cs(const float* p) {
    float4 f0 = __ldcs((const float4*)p);
    float4 f1 = __ldcs((const float4*)(p + 4));
    __half2 h0 = __floats2half2_rn(f0.x, f0.y);
    __half2 h1 = __floats2half2_rn(f0.z, f0.w);
    __half2 h2 = __floats2half2_rn(f1.x, f1.y);
    __half2 h3 = __floats2half2_rn(f1.z, f1.w);
    uint4 r;
    r.x = *reinterpret_cast<uint32_t*>(&h0);
    r.y = *reinterpret_cast<uint32_t*>(&h1);
    r.z = *reinterpret_cast<uint32_t*>(&h2);
    r.w = *reinterpret_cast<uint32_t*>(&h3);
    return r;
}
__device__ __forceinline__ void ld4f(const __half* p, float* f) {
    uint2 u = *(const uint2*)p;
    float2 fa = __half22float2(*(__half2*)&u.x);
    float2 fb = __half22float2(*(__half2*)&u.y);
    f[0] = fa.x; f[1] = fa.y; f[2] = fb.x; f[3] = fb.y;
}
__device__ __forceinline__ void ld4f(const float* p, float* f) {
    float4 v = *(const float4*)p;
    f[0] = v.x; f[1] = v.y; f[2] = v.z; f[3] = v.w;
}
// streaming (evict-first) variants for once-read KV cache rows
__device__ __forceinline__ void ld4f_cs(const __half* p, float* f) {
    uint2 u = __ldcs((const uint2*)p);
    float2 fa = __half22float2(*(__half2*)&u.x);
    float2 fb = __half22float2(*(__half2*)&u.y);
    f[0] = fa.x; f[1] = fa.y; f[2] = fb.x; f[3] = fb.y;
}
__device__ __forceinline__ void ld4f_cs(const float* p, float* f) {
    float4 v = __ldcs((const float4*)p);
    f[0] = v.x; f[1] = v.y; f[2] = v.z; f[3] = v.w;
}
__device__ __forceinline__ float ldf1(const void* p, int i) {
    return g_isf32 ? ((const float*)p)[i] : __half2float(((const __half*)p)[i]);
}

// ---------------------------------------------------------------------------
// m16n8k16 f16 MMA (f32 accumulate)
// ---------------------------------------------------------------------------
__device__ __forceinline__ void mma16816(float* d,
                                         uint32_t a0, uint32_t a1, uint32_t a2, uint32_t a3,
                                         uint32_t b0, uint32_t b1) {
    asm volatile(
        "mma.sync.aligned.m16n8k16.row.col.f32.f16.f16.f32 "
        "{%0,%1,%2,%3},{%4,%5,%6,%7},{%8,%9},{%0,%1,%2,%3};\n"
        : "+f"(d[0]), "+f"(d[1]), "+f"(d[2]), "+f"(d[3])
        : "r"(a0), "r"(a1), "r"(a2), "r"(a3), "r"(b0), "r"(b1));
}

// ---------------------------------------------------------------------------
// Kernel 1: x convert to fp16 (+ fused dtype probe)
// ---------------------------------------------------------------------------
__global__ void __launch_bounds__(256) xconv_kernel(const void* xv) {
    int e0 = (blockIdx.x * 256 + threadIdx.x) * 8;
    const uint32_t* w = (const uint32_t*)xv + (e0 >> 1);
    int good16 = 0, good32 = 0;
#pragma unroll
    for (int i = 0; i < 4; i++) {
        uint32_t u = w[i];
        float a = __half2float(__ushort_as_half((unsigned short)(u & 0xFFFFu)));
        float bb = __half2float(__ushort_as_half((unsigned short)(u >> 16)));
        if (isfinite(a) && isfinite(bb) &&
            fabsf(a) > 0.004f && fabsf(a) < 8.f &&
            fabsf(bb) > 0.004f && fabsf(bb) < 8.f) good16++;
        float f = __uint_as_float(u);
        if (isfinite(f) && fabsf(f) > 0.004f && fabsf(f) < 8.f) good32++;
    }
#pragma unroll
    for (int off = 16; off > 0; off >>= 1) {
        good16 += __shfl_xor_sync(0xffffffffu, good16, off);
        good32 += __shfl_xor_sync(0xffffffffu, good32, off);
    }
    int isf32 = good32 > good16;
    if (blockIdx.x == 0 && threadIdx.x == 0) g_isf32 = isf32;

    uint4 out;
    if (isf32) out = ld8((const float*)xv + e0);
    else       out = *((const uint4*)xv + (e0 >> 3));
    *(uint4*)(g_x + e0) = out;
}

// ---------------------------------------------------------------------------
// Kernel 2: QKV projection, split-K=8, unroll 4 (R14 config), streaming weights.
// grid = 96*8 = 768 blocks x 256.
// ---------------------------------------------------------------------------
template<typename T>
__device__ __forceinline__ void qkv_sk(const T* __restrict__ w, int wrow0,
                                       float* __restrict__ out, int ocol0, int k0) {
    const int warp = threadIdx.x >> 5;
    const int lane = threadIdx.x & 31;
    const int g = lane >> 2;
    const int c = lane & 3;

    const T* wrow = w + (size_t)(wrow0 + warp * 8 + g) * HID + k0 + 8 * c;
    const __half* x0 = g_x + (size_t)g * HID + k0 + 8 * c;

    float d0[4] = {0.f, 0.f, 0.f, 0.f};
    float d1[4] = {0.f, 0.f, 0.f, 0.f};

#pragma unroll 4
    for (int kb = 0; kb < KSLICE; kb += 32) {
        uint4 bv = ld8_cs(wrow + kb);
        uint4 xa = ld8(x0 + kb);
        uint4 xb = ld8(x0 + 8 * HID + kb);
        uint4 xc = ld8(x0 + 16 * HID + kb);
        uint4 xd = ld8(x0 + 24 * HID + kb);
        mma16816(d0, xa.x, xb.x, xa.y, xb.y, bv.x, bv.y);
        mma16816(d1, xc.x, xd.x, xc.y, xd.y, bv.x, bv.y);
        mma16816(d0, xa.z, xb.z, xa.w, xb.w, bv.z, bv.w);
        mma16816(d1, xc.z, xd.z, xc.w, xd.w, bv.z, bv.w);
    }

    const int oc = ocol0 + warp * 8 + 2 * c;
    *(float2*)(out + (size_t)(g)      * NCOLS + oc) = make_float2(d0[0], d0[1]);
    *(float2*)(out + (size_t)(g + 8)  * NCOLS + oc) = make_float2(d0[2], d0[3]);
    *(float2*)(out + (size_t)(g + 16) * NCOLS + oc) = make_float2(d1[0], d1[1]);
    *(float2*)(out + (size_t)(g + 24) * NCOLS + oc) = make_float2(d1[2], d1[3]);
}
__global__ void __launch_bounds__(256) qkv_kernel(const void* wq, const void* wk, const void* wv) {
    int nt = blockIdx.x >> 3;
    int ks = blockIdx.x & 7;
    int ncol = nt * 64;
    int k0 = ks * KSLICE;
    float* out = g_qkvp + (size_t)ks * NB * NCOLS;
    const void* w;
    int wrow0;
    if (ncol < 4096)      { w = wq; wrow0 = ncol; }
    else if (ncol < 5120) { w = wk; wrow0 = ncol - 4096; }
    else                  { w = wv; wrow0 = ncol - 5120; }
    if (g_isf32) qkv_sk<float >((const float*)w, wrow0, out, ncol, k0);
    else         qkv_sk<__half>((const __half*)w, wrow0, out, ncol, k0);
}

// ---------------------------------------------------------------------------
// Kernel 3: qkv combine -> g_q / g_k / g_v (fp16)
// ---------------------------------------------------------------------------
__global__ void __launch_bounds__(256) qkvcomb_kernel() {
    int idx = blockIdx.x * 256 + threadIdx.x;
    int m = idx / NCOLS, ncol = idx - m * NCOLS;
    float s = 0.f;
#pragma unroll
    for (int ks = 0; ks < SPLITK; ks++) s += g_qkvp[(size_t)ks * NB * NCOLS + idx];
    __half h = __float2half(s);
    if (ncol < 4096)      g_q[m * 4096 + ncol] = h;
    else if (ncol < 5120) g_k[m * 1024 + ncol - 4096] = h;
    else                  g_v[m * 1024 + ncol - 5120] = h;
}

// ---------------------------------------------------------------------------
// Kernel 4: split-K flash-decode attention (R14 body, byte-identical).
// grid = NGRP * ASPLIT = 1024 blocks x 256 threads.
// ---------------------------------------------------------------------------
#define ATTN_SMEM_BYTES (CHUNK*KROW*2*2 + 512*4 /*q*/ + CHUNK*4*4 /*p*/ + 16*CHUNK*4 /*s_part*/ + 64*4)

template<typename T>
__device__ __forceinline__ void attn_body(const T* __restrict__ kv,
                                          const int* __restrict__ sel,
                                          const void* __restrict__ cos_,
                                          const void* __restrict__ sin_) {
    extern __shared__ char smem_raw[];
    __half* k_sm   = (__half*)smem_raw;                 // [CHUNK][KROW]
    __half* v_sm   = k_sm + CHUNK * KROW;               // [CHUNK][KROW]
    float*  q_sm   = (float*)(v_sm + CHUNK * KROW);     // [4][128]
    float*  p_sm   = q_sm + 512;                        // [4][CHUNK]
    float*  s_part = p_sm + 4 * CHUNK;                  // [4][4][CHUNK]
    float*  wred   = s_part + 16 * CHUNK;               // [8]
    float*  m_run  = wred + 8;                          // [4]
    float*  l_run  = m_run + 4;                         // [4]
    float*  al_sm  = l_run + 4;                         // [4]

    const int grp  = blockIdx.x >> 2;
    const int sp   = blockIdx.x & 3;
    const int b    = grp >> 3;
    const int gq   = grp & 7;
    const int t    = threadIdx.x;
    const int warp = t >> 5;
    const int lane = t & 31;
    const float scale = 0.08838834764831845f;

    // q into smem with RoPE fused
    for (int i = t; i < 512; i += 256) {
        int r = i >> 7, d = i & 127;
        const __half* qr = g_q + (size_t)(b * NHQ + gq * 4 + r) * HDIM;
        float q0 = __half2float(qr[d]);
        float q1 = __half2float(qr[d ^ 64]);
        float cv = ldf1(cos_, b * HDIM + d);
        float sv = ldf1(sin_, b * HDIM + d);
        float rot = (d < 64) ? -q1 : q1;
        q_sm[i] = fmaf(q0, cv, rot * sv) * scale;
    }
    if (t < 4) { m_run[t] = -1e30f; l_run[t] = 0.f; }
    __syncthreads();

    float o[4][4];
#pragma unroll
    for (int r = 0; r < 4; r++)
#pragma unroll
        for (int i = 0; i < 4; i++) o[r][i] = 0.f;

    // Last split's prologue: the new token (roped k)
    if (sp == ASPLIT - 1) {
        if (warp < 4) {
            const int r = warp;
            const __half* kr = g_k + (size_t)(b * NKVH + gq) * HDIM;
            float part = 0.f;
            const float* qrp = q_sm + r * 128 + lane * 4;
#pragma unroll
            for (int i = 0; i < 4; i++) {
                int d = lane * 4 + i;
                float k0 = __half2float(kr[d]);
                float k1 = __half2float(kr[d ^ 64]);
                float cv = ldf1(cos_, b * HDIM + d);
                float sv = ldf1(sin_, b * HDIM + d);
                float rot = (d < 64) ? -k1 : k1;
                part = fmaf(qrp[i], fmaf(k0, cv, rot * sv), part);
            }
#pragma unroll
            for (int off = 16; off > 0; off >>= 1)
                part += __shfl_xor_sync(0xffffffffu, part, off);
            if (lane == 0) { m_run[r] = part; l_run[r] = 1.f; }
        }
        if (warp == 0) {
            float vf[4];
            ld4f(g_v + (size_t)(b * NKVH + gq) * HDIM + lane * 4, vf);
#pragma unroll
            for (int r = 0; r < 4; r++)
#pragma unroll
                for (int i = 0; i < 4; i++) o[r][i] = vf[i];
        }
        __syncthreads();
    }

    const int selbase = b * PASTLEN;

    for (int ch = 0; ch < CH_PER_S; ch++) {
        const int key0 = (sp * CH_PER_S + ch) * CHUNK;

        // stage K/V -> smem fp16 : warp w handles rows [8w, 8w+8); streaming loads
#pragma unroll
        for (int i = 0; i < CHUNK / 8; i++) {
            int j = warp * (CHUNK / 8) + i;
            int row = __ldg(sel + selbase + key0 + j);
            const T* kp = kv + (size_t)row * (2 * NKVH * HDIM) + gq * HDIM + lane * 4;
            const T* vp = kp + NKVH * HDIM;
            float kf[4], vf[4];
            ld4f_cs(kp, kf);
            ld4f_cs(vp, vf);
            __half2 ka = __floats2half2_rn(kf[0], kf[1]);
            __half2 kb = __floats2half2_rn(kf[2], kf[3]);
            __half2 va = __floats2half2_rn(vf[0], vf[1]);
            __half2 vb = __floats2half2_rn(vf[2], vf[3]);
            uint2 kw, vw;
            kw.x = *reinterpret_cast<uint32_t*>(&ka); kw.y = *reinterpret_cast<uint32_t*>(&kb);
            vw.x = *reinterpret_cast<uint32_t*>(&va); vw.y = *reinterpret_cast<uint32_t*>(&vb);
            *(uint2*)(k_sm + j * KROW + lane * 4) = kw;
            *(uint2*)(v_sm + j * KROW + lane * 4) = vw;
        }
        __syncthreads();

        // scores: thread -> (key j = t&63, quarter qh = t>>6 -> dims [32qh, 32qh+32))
        {
            const int j  = t & 63;
            const int qh = t >> 6;
            const __half* kr = k_sm + j * KROW + qh * 32;
            const float* q0 = q_sm + 0 * 128 + qh * 32;
            const float* q1 = q_sm + 1 * 128 + qh * 32;
            const float* q2 = q_sm + 2 * 128 + qh * 32;
            const float* q3 = q_sm + 3 * 128 + qh * 32;
            float s0 = 0.f, s1 = 0.f, s2 = 0.f, s3 = 0.f;
#pragma unroll
            for (int d = 0; d < 32; d += 4) {
                float kf[4];
                ld4f(kr + d, kf);
                float4 a0 = *(const float4*)(q0 + d);
                float4 a1 = *(const float4*)(q1 + d);
                float4 a2 = *(const float4*)(q2 + d);
                float4 a3 = *(const float4*)(q3 + d);
                s0 = fmaf(a0.x, kf[0], fmaf(a0.y, kf[1], fmaf(a0.z, kf[2], fmaf(a0.w, kf[3], s0))));
                s1 = fmaf(a1.x, kf[0], fmaf(a1.y, kf[1], fmaf(a1.z, kf[2], fmaf(a1.w, kf[3], s1))));
                s2 = fmaf(a2.x, kf[0], fmaf(a2.y, kf[1], fmaf(a2.z, kf[2], fmaf(a2.w, kf[3], s2))));
                s3 = fmaf(a3.x, kf[0], fmaf(a3.y, kf[1], fmaf(a3.z, kf[2], fmaf(a3.w, kf[3], s3))));
            }
            s_part[(qh * 4 + 0) * CHUNK + j] = s0;
            s_part[(qh * 4 + 1) * CHUNK + j] = s1;
            s_part[(qh * 4 + 2) * CHUNK + j] = s2;
            s_part[(qh * 4 + 3) * CHUNK + j] = s3;
        }
        __syncthreads();

        // block softmax: thread -> (head r = t>>6, key j = t&63)
        {
            const int r = t >> 6;
            const int j = t & 63;
            float s = s_part[(0 * 4 + r) * CHUNK + j] + s_part[(1 * 4 + r) * CHUNK + j]
                    + s_part[(2 * 4 + r) * CHUNK + j] + s_part[(3 * 4 + r) * CHUNK + j];
            float mx = s;
#pragma unroll
            for (int off = 16; off > 0; off >>= 1)
                mx = fmaxf(mx, __shfl_xor_sync(0xffffffffu, mx, off));
            if (lane == 0) wred[warp] = mx;
            __syncthreads();
            if (t < 4) {
                float mn = fmaxf(m_run[t], fmaxf(wred[2 * t], wred[2 * t + 1]));
                al_sm[t] = __expf(m_run[t] - mn);
                m_run[t] = mn;
            }
            __syncthreads();
            float p = __expf(s - m_run[r]);
            p_sm[r * CHUNK + j] = p;
            float ps = p;
#pragma unroll
            for (int off = 16; off > 0; off >>= 1)
                ps += __shfl_xor_sync(0xffffffffu, ps, off);
            if (lane == 0) wred[warp] = ps;
            __syncthreads();
            if (t < 4)
                l_run[t] = l_run[t] * al_sm[t] + wred[2 * t] + wred[2 * t + 1];
        }

        // PV: warp w -> keys j ≡ w (mod 8)
        {
            float a0 = al_sm[0], a1 = al_sm[1], a2 = al_sm[2], a3 = al_sm[3];
#pragma unroll
            for (int i = 0; i < 4; i++) {
                o[0][i] *= a0; o[1][i] *= a1; o[2][i] *= a2; o[3][i] *= a3;
            }
#pragma unroll
            for (int kk = 0; kk < CHUNK / 8; kk++) {
                int j = warp + kk * 8;
                float vf[4];
                ld4f(v_sm + j * KROW + lane * 4, vf);
                float p0 = p_sm[0 * CHUNK + j];
                float p1 = p_sm[1 * CHUNK + j];
                float p2 = p_sm[2 * CHUNK + j];
                float p3 = p_sm[3 * CHUNK + j];
#pragma unroll
                for (int i = 0; i < 4; i++) {
                    o[0][i] = fmaf(p0, vf[i], o[0][i]);
                    o[1][i] = fmaf(p1, vf[i], o[1][i]);
                    o[2][i] = fmaf(p2, vf[i], o[2][i]);
                    o[3][i] = fmaf(p3, vf[i], o[3][i]);
                }
            }
        }
        __syncthreads();
    }

    // merge 8 per-warp accumulators, write unnormalized split result
    float* scratch = (float*)smem_raw;
#pragma unroll
    for (int r = 0; r < 4; r++) {
        float4 v = make_float4(o[r][0], o[r][1], o[r][2], o[r][3]);
        *(float4*)(scratch + (warp * 512 + r * 128 + lane * 4)) = v;
    }
    __syncthreads();
    for (int s = t; s < 512; s += 256) {
        float acc = 0.f;
#pragma unroll
        for (int w = 0; w < 8; w++) acc += scratch[w * 512 + s];
        g_po[(size_t)blockIdx.x * 512 + s] = acc;
    }
    if (t < 4) {
        g_pm[blockIdx.x * 4 + t] = m_run[t];
        g_pl[blockIdx.x * 4 + t] = l_run[t];
    }
}
__global__ void __launch_bounds__(256) attn_kernel(const void* kv, const int* sel,
                                                   const void* cos_, const void* sin_) {
    if (g_isf32) attn_body<float>((const float*)kv, sel, cos_, sin_);
    else         attn_body<__half>((const __half*)kv, sel, cos_, sin_);
}

// ---------------------------------------------------------------------------
// Kernel 4b: merge ASPLIT splits per group -> g_attn
// grid = NGRP (256), block = 512
// ---------------------------------------------------------------------------
__global__ void __launch_bounds__(512) attncomb_kernel() {
    const int grp = blockIdx.x;
    const int r = threadIdx.x >> 7;
    const int d = threadIdx.x & 127;
    const int b = grp >> 3, gq = grp & 7;

    float ms[ASPLIT];
    float M = -1e30f;
#pragma unroll
    for (int s = 0; s < ASPLIT; s++) {
        ms[s] = g_pm[(grp * ASPLIT + s) * 4 + r];
        M = fmaxf(M, ms[s]);
    }
    float L = 0.f, O = 0.f;
#pragma unroll
    for (int s = 0; s < ASPLIT; s++) {
        float al = __expf(ms[s] - M);
        L = fmaf(al, g_pl[(grp * ASPLIT + s) * 4 + r], L);
        O = fmaf(al, g_po[(size_t)(grp * ASPLIT + s) * 512 + r * 128 + d], O);
    }
    g_attn[(size_t)(b * NHQ + gq * 4 + r) * HDIM + d] = __float2half(O / L);
}

// ---------------------------------------------------------------------------
// Kernel 5: output projection, split-K=8, wo transposed tile-wise in smem
// (R14 single-buffer config), streaming wo loads.
// ---------------------------------------------------------------------------
#define WTROW 72

__global__ void __launch_bounds__(256) outproj_kernel(const void* wo) {
    __shared__ __align__(16) __half wt[64 * WTROW];

    const int nt = blockIdx.x >> 3;
    const int ks = blockIdx.x & 7;
    const int h0 = nt * 64;
    const int k0 = ks * KSLICE;

    const int t    = threadIdx.x;
    const int warp = t >> 5;
    const int lane = t & 31;
    const int g = lane >> 2;
    const int c = lane & 3;
    const int tx = t & 63;
    const int ty = t >> 6;

    float d0[4] = {0.f, 0.f, 0.f, 0.f};
    float d1[4] = {0.f, 0.f, 0.f, 0.f};

    const __half* x0 = g_attn + (size_t)g * HID + 8 * c;
    const int isf = g_isf32;

    for (int chv = 0; chv < KSLICE / 64; chv++) {
        const int o0 = k0 + chv * 64;
        if (isf) {
            const float* W = (const float*)wo;
#pragma unroll
            for (int j = ty; j < 64; j += 4)
                wt[tx * WTROW + j] = __float2half(__ldcs(W + (size_t)(o0 + j) * HID + h0 + tx));
        } else {
            const __half* W = (const __half*)wo;
#pragma unroll
            for (int j = ty; j < 64; j += 4)
                wt[tx * WTROW + j] = __ldcs(W + (size_t)(o0 + j) * HID + h0 + tx);
        }
        __syncthreads();

#pragma unroll
        for (int kb = 0; kb < 64; kb += 32) {
            uint4 bv = *(const uint4*)(wt + (warp * 8 + g) * WTROW + kb + 8 * c);
            uint4 xa = ld8(x0 + o0 + kb);
            uint4 xb = ld8(x0 + 8 * HID + o0 + kb);
            uint4 xc = ld8(x0 + 16 * HID + o0 + kb);
            uint4 xd = ld8(x0 + 24 * HID + o0 + kb);
            mma16816(d0, xa.x, xb.x, xa.y, xb.y, bv.x, bv.y);
            mma16816(d1, xc.x, xd.x, xc.y, xd.y, bv.x, bv.y);
            mma16816(d0, xa.z, xb.z, xa.w, xb.w, bv.z, bv.w);
            mma16816(d1, xc.z, xd.z, xc.w, xd.w, bv.z, bv.w);
        }
        __syncthreads();
    }

    float* out = g_op + (size_t)ks * NB * HID;
    const int oc = h0 + warp * 8 + 2 * c;
    *(float2*)(out + (size_t)(g)      * HID + oc) = make_float2(d0[0], d0[1]);
    *(float2*)(out + (size_t)(g + 8)  * HID + oc) = make_float2(d0[2], d0[3]);
    *(float2*)(out + (size_t)(g + 16) * HID + oc) = make_float2(d1[0], d1[1]);
    *(float2*)(out + (size_t)(g + 24) * HID + oc) = make_float2(d1[2], d1[3]);
}

// ---------------------------------------------------------------------------
// Kernel 6: out combine -> d_out (typed)
// ---------------------------------------------------------------------------
__global__ void __launch_bounds__(256) outcomb_kernel(void* y) {
    int idx = blockIdx.x * 256 + threadIdx.x;
    float s = 0.f;
#pragma unroll
    for (int ks = 0; ks < SPLITK; ks++) s += g_op[(size_t)ks * NB * HID + idx];
    if (g_isf32) ((float*)y)[idx] = s;
    else         ((__half*)y)[idx] = __float2half(s);
}

// ---------------------------------------------------------------------------
extern "C" void kernel_launch(void* const* d_in, const int* in_sizes, int n_in,
                              void* d_out, int out_size) {
    (void)out_size;
    const void *x = nullptr, *wq = nullptr, *wk = nullptr, *wv = nullptr, *wo = nullptr;
    const void *cosp = nullptr, *sinp = nullptr, *kvb = nullptr;
    const int* sel = nullptr;
    int ix = -1, ibig0 = -1, ibig1 = -1;
    for (int i = 0; i < n_in; i++) {
        int s = in_sizes[i];
        if      (s == 131072)    { x = d_in[i]; ix = i; }
        else if (s == 136314880) { kvb = d_in[i]; }
        else if (s == 65536)     { sel = (const int*)d_in[i]; }
        else if (s == 16777216)  { if (ibig0 < 0) ibig0 = i; else ibig1 = i; }
        else if (s == 4194304)   { if (!wk) wk = d_in[i]; else wv = d_in[i]; }
        else if (s == 4096)      { if (!cosp) cosp = d_in[i]; else sinp = d_in[i]; }
    }
    if (ibig0 == ix + 1)      { wq = d_in[ibig0]; wo = d_in[ibig1]; }   // dict order
    else if (ix == n_in - 1)  { wo = d_in[ibig0]; wq = d_in[ibig1]; }   // alphabetical
    else                      { wq = d_in[ibig0]; wo = d_in[ibig1]; }

    static int smem_set = 0;
    if (!smem_set) {
        cudaFuncSetAttribute(attn_kernel, cudaFuncAttributeMaxDynamicSharedMemorySize,
                             ATTN_SMEM_BYTES);
        smem_set = 1;
    }

    xconv_kernel<<<64, 256>>>(x);
    qkv_kernel<<<96 * SPLITK, 256>>>(wq, wk, wv);
    qkvcomb_kernel<<<NB * NCOLS / 256, 256>>>();
    attn_kernel<<<NGRP * ASPLIT, 256, ATTN_SMEM_BYTES>>>(kvb, sel, cosp, sinp);
    attncomb_kernel<<<NGRP, 512>>>();
    outproj_kernel<<<64 * SPLITK, 256>>>(wo);
    outcomb_kernel<<<NB * HID / 256, 256>>>(d_out);
}